// round 5
// baseline (speedup 1.0000x reference)
#include <cuda_runtime.h>
#include <stdint.h>

#define N_NODES 50000
#define DIM     128        // D == O == 128
#define E_MAX   800016     // per-relation edge capacity (problem fixes E=800000)
#define A_PAD   132        // shared A row stride (bank-conflict-free fragments)

// ---------------------------------------------------------------------------
// Static scratch (no cudaMalloc allowed).
// ---------------------------------------------------------------------------
__device__ float g_x1[N_NODES * DIM];        // in @ W1   (25.6 MB)
__device__ float g_x2[N_NODES * DIM];        // in @ W2   (25.6 MB)

// Flattened CSR over "global rows" g = rel*N + row  (2N rows total).
__device__ int  g_cnt[2 * N_NODES];          // per-row edge counts
__device__ int  g_off[2 * N_NODES + 1];      // exclusive prefix (CSR row ptr)
__device__ int  g_pos[2 * N_NODES];          // running insert cursor (scatter)
__device__ int2 g_edge[2 * E_MAX];           // packed (col, val-bits) per edge

__device__ __forceinline__ uint32_t f2tf32(float f) {
    uint32_t r;
    asm("cvt.rna.tf32.f32 %0, %1;" : "=r"(r) : "f"(f));
    return r;
}

// ---------------------------------------------------------------------------
// Dense projection on tensor cores: x = in @ W per relation (blockIdx.y).
// (unchanged from R3: 44 us, tensor-pipe active)
// ---------------------------------------------------------------------------
__global__ void __launch_bounds__(256)
gemm_tf32_kernel(const float* __restrict__ in,
                 const float* __restrict__ W1,
                 const float* __restrict__ W2)
{
    __shared__ uint32_t shA[64 * A_PAD];

    const int tid  = threadIdx.x;
    const int warp = tid >> 5;
    const int lane = tid & 31;
    const int row0 = blockIdx.x * 64;
    const float* __restrict__ W    = blockIdx.y ? W2   : W1;
    float*       __restrict__ xout = blockIdx.y ? g_x2 : g_x1;

    #pragma unroll
    for (int i = 0; i < 8; ++i) {
        int idx = tid + i * 256;
        int r   = idx >> 5;
        int c4  = idx & 31;
        float4 v = make_float4(0.f, 0.f, 0.f, 0.f);
        if (row0 + r < N_NODES)
            v = __ldg(reinterpret_cast<const float4*>(in + (size_t)(row0 + r) * DIM) + c4);
        uint32_t* s = shA + r * A_PAD + c4 * 4;
        s[0] = f2tf32(v.x); s[1] = f2tf32(v.y); s[2] = f2tf32(v.z); s[3] = f2tf32(v.w);
    }
    __syncthreads();

    const int col0 = warp * 16;
    uint32_t Bf[2][16][2];
    #pragma unroll
    for (int nt = 0; nt < 2; ++nt) {
        const int n = col0 + nt * 8 + (lane >> 2);
        #pragma unroll
        for (int kk = 0; kk < 16; ++kk) {
            const int k = kk * 8 + (lane & 3);
            Bf[nt][kk][0] = f2tf32(__ldg(W + k * DIM + n));
            Bf[nt][kk][1] = f2tf32(__ldg(W + (k + 4) * DIM + n));
        }
    }

    #pragma unroll
    for (int rt = 0; rt < 4; ++rt) {
        float acc[2][4] = {};
        const uint32_t* sA = shA + (rt * 16) * A_PAD;
        #pragma unroll
        for (int kk = 0; kk < 16; ++kk) {
            const int r = lane >> 2, c = kk * 8 + (lane & 3);
            uint32_t a0 = sA[r * A_PAD + c];
            uint32_t a1 = sA[(r + 8) * A_PAD + c];
            uint32_t a2 = sA[r * A_PAD + c + 4];
            uint32_t a3 = sA[(r + 8) * A_PAD + c + 4];
            #pragma unroll
            for (int nt = 0; nt < 2; ++nt) {
                asm volatile(
                    "mma.sync.aligned.m16n8k8.row.col.f32.tf32.tf32.f32 "
                    "{%0,%1,%2,%3}, {%4,%5,%6,%7}, {%8,%9}, {%0,%1,%2,%3};"
                    : "+f"(acc[nt][0]), "+f"(acc[nt][1]),
                      "+f"(acc[nt][2]), "+f"(acc[nt][3])
                    : "r"(a0), "r"(a1), "r"(a2), "r"(a3),
                      "r"(Bf[nt][kk][0]), "r"(Bf[nt][kk][1]));
            }
        }
        const int rowa = row0 + rt * 16 + (lane >> 2);
        const int rowb = rowa + 8;
        #pragma unroll
        for (int nt = 0; nt < 2; ++nt) {
            const int c = col0 + nt * 8 + 2 * (lane & 3);
            if (rowa < N_NODES)
                *reinterpret_cast<float2*>(xout + (size_t)rowa * DIM + c) =
                    make_float2(acc[nt][0], acc[nt][1]);
            if (rowb < N_NODES)
                *reinterpret_cast<float2*>(xout + (size_t)rowb * DIM + c) =
                    make_float2(acc[nt][2], acc[nt][3]);
        }
    }
}

// ---------------------------------------------------------------------------
// CSR build, stage 0: zero counters.
// ---------------------------------------------------------------------------
__global__ void __launch_bounds__(256)
zero_cnt_kernel()
{
    const int i = blockIdx.x * blockDim.x + threadIdx.x;
    if (i < 2 * N_NODES) g_cnt[i] = 0;
}

// Stage 1: per-row histogram over both relations (flattened row id).
__global__ void __launch_bounds__(256)
hist_kernel(const int* __restrict__ r1, const int* __restrict__ r2,
            int E1, int Etot)
{
    const int e = blockIdx.x * blockDim.x + threadIdx.x;
    if (e >= Etot) return;
    const int g = (e < E1) ? __ldg(r1 + e) : N_NODES + __ldg(r2 + e - E1);
    atomicAdd(&g_cnt[g], 1);
}

// Stage 2: exclusive prefix sum over 2N counts (single 1024-thread block).
__global__ void __launch_bounds__(1024)
scan_kernel()
{
    __shared__ int part[1024];
    const int T  = 1024;
    const int CH = (2 * N_NODES + T - 1) / T;          // 98
    const int t  = threadIdx.x;
    const int b  = t * CH;
    const int e  = (b + CH < 2 * N_NODES) ? b + CH : 2 * N_NODES;

    int s = 0;
    for (int i = b; i < e; ++i) s += g_cnt[i];
    part[t] = s;
    __syncthreads();

    // Hillis-Steele inclusive scan of partials.
    #pragma unroll
    for (int d = 1; d < T; d <<= 1) {
        int v = (t >= d) ? part[t - d] : 0;
        __syncthreads();
        part[t] += v;
        __syncthreads();
    }

    int base = (t == 0) ? 0 : part[t - 1];
    for (int i = b; i < e; ++i) {
        g_off[i] = base;
        g_pos[i] = base;
        base += g_cnt[i];
    }
    if (t == T - 1) g_off[2 * N_NODES] = part[T - 1];  // total edge count
}

// Stage 3: scatter edges into CSR order, packed (col, val).
__global__ void __launch_bounds__(256)
scatter_kernel(const int* __restrict__ r1, const int* __restrict__ c1,
               const float* __restrict__ v1,
               const int* __restrict__ r2, const int* __restrict__ c2,
               const float* __restrict__ v2,
               int E1, int Etot)
{
    const int e = blockIdx.x * blockDim.x + threadIdx.x;
    if (e >= Etot) return;
    int g, c; float v;
    if (e < E1) {
        g = __ldg(r1 + e);           c = __ldg(c1 + e); v = __ldg(v1 + e);
    } else {
        const int e2 = e - E1;
        g = N_NODES + __ldg(r2 + e2); c = __ldg(c2 + e2); v = __ldg(v2 + e2);
    }
    const int p = atomicAdd(&g_pos[g], 1);
    g_edge[p] = make_int2(c, __float_as_int(v));
}

// ---------------------------------------------------------------------------
// Segmented SpMM: one warp per output row. Accumulates both relations in
// registers (lane owns a float4 of columns), fuses ReLU, writes out ONCE.
// No atomics, no memset, no separate relu pass.
// ---------------------------------------------------------------------------
__device__ __forceinline__ void row_accum(const float* __restrict__ x,
                                          int s, int e, int lane, float4& acc)
{
    int i = s;
    for (; i + 1 < e; i += 2) {                     // 2x unroll for MLP
        const int2 ed0 = __ldg(&g_edge[i]);
        const int2 ed1 = __ldg(&g_edge[i + 1]);
        const float  v0 = __int_as_float(ed0.y);
        const float  v1 = __int_as_float(ed1.y);
        const float4 x0 = __ldg(reinterpret_cast<const float4*>(x + (size_t)ed0.x * DIM) + lane);
        const float4 x1 = __ldg(reinterpret_cast<const float4*>(x + (size_t)ed1.x * DIM) + lane);
        acc.x = fmaf(v0, x0.x, acc.x); acc.y = fmaf(v0, x0.y, acc.y);
        acc.z = fmaf(v0, x0.z, acc.z); acc.w = fmaf(v0, x0.w, acc.w);
        acc.x = fmaf(v1, x1.x, acc.x); acc.y = fmaf(v1, x1.y, acc.y);
        acc.z = fmaf(v1, x1.z, acc.z); acc.w = fmaf(v1, x1.w, acc.w);
    }
    if (i < e) {
        const int2 ed = __ldg(&g_edge[i]);
        const float  v  = __int_as_float(ed.y);
        const float4 xv = __ldg(reinterpret_cast<const float4*>(x + (size_t)ed.x * DIM) + lane);
        acc.x = fmaf(v, xv.x, acc.x); acc.y = fmaf(v, xv.y, acc.y);
        acc.z = fmaf(v, xv.z, acc.z); acc.w = fmaf(v, xv.w, acc.w);
    }
}

__global__ void __launch_bounds__(256)
spmm_csr_kernel(float* __restrict__ out)
{
    const int row  = (blockIdx.x * blockDim.x + threadIdx.x) >> 5;
    const int lane = threadIdx.x & 31;
    if (row >= N_NODES) return;

    float4 acc = make_float4(0.f, 0.f, 0.f, 0.f);

    // Relation 0: flattened rows [0, N). off[row+1] is valid even at row=N-1
    // (it is rel1-row0's start == rel0's end) because the layout is contiguous.
    row_accum(g_x1, g_off[row],           g_off[row + 1],           lane, acc);
    // Relation 1: flattened rows [N, 2N), terminated by g_off[2N] = Etot.
    row_accum(g_x2, g_off[N_NODES + row], g_off[N_NODES + row + 1], lane, acc);

    acc.x = fmaxf(acc.x, 0.f); acc.y = fmaxf(acc.y, 0.f);
    acc.z = fmaxf(acc.z, 0.f); acc.w = fmaxf(acc.w, 0.f);
    reinterpret_cast<float4*>(out + (size_t)row * DIM)[lane] = acc;
}

// ---------------------------------------------------------------------------
// Entry point. Inputs (metadata order):
//   0 inputs[N,128] f32 | 1 adj1_rows i32 | 2 adj1_cols i32 | 3 adj1_vals f32
//   4 adj2_rows i32 | 5 adj2_cols i32 | 6 adj2_vals f32
//   7 weights_1[128,128] f32 | 8 weights_2[128,128] f32
// Output: [N,128] f32.
// ---------------------------------------------------------------------------
extern "C" void kernel_launch(void* const* d_in, const int* in_sizes, int n_in,
                              void* d_out, int out_size)
{
    const float* in  = (const float*)d_in[0];
    const int*   a1r = (const int*)  d_in[1];
    const int*   a1c = (const int*)  d_in[2];
    const float* a1v = (const float*)d_in[3];
    const int*   a2r = (const int*)  d_in[4];
    const int*   a2c = (const int*)  d_in[5];
    const float* a2v = (const float*)d_in[6];
    const float* W1  = (const float*)d_in[7];
    const float* W2  = (const float*)d_in[8];
    float*       out = (float*)d_out;

    const int E1   = in_sizes[1];
    const int E2   = in_sizes[4];
    const int Etot = E1 + E2;

    const int eblk = (Etot + 255) / 256;

    // CSR build (counting sort by row, both relations flattened).
    zero_cnt_kernel<<<(2 * N_NODES + 255) / 256, 256>>>();
    hist_kernel<<<eblk, 256>>>(a1r, a2r, E1, Etot);
    scan_kernel<<<1, 1024>>>();
    scatter_kernel<<<eblk, 256>>>(a1r, a1c, a1v, a2r, a2c, a2v, E1, Etot);

    // Tensor-core projections (both relations, grid.y = relation).
    dim3 ggrid((N_NODES + 63) / 64, 2);
    gemm_tf32_kernel<<<ggrid, 256>>>(in, W1, W2);

    // Segmented SpMM + fused ReLU: one warp per row, single non-atomic store.
    spmm_csr_kernel<<<(N_NODES * 32 + 255) / 256, 256>>>(out);
}

// round 6
// speedup vs baseline: 1.9892x; 1.9892x over previous
#include <cuda_runtime.h>
#include <stdint.h>

#define N_NODES 50000
#define DIM     128        // D == O == 128
#define E_MAX   800016     // per-relation edge capacity (problem fixes E=800000)
#define A_PAD   132        // shared A row stride (bank-conflict-free fragments)

#define NROWS2  (2 * N_NODES)                 // flattened rows (2 relations)
#define SCAN_B  256
#define NBLK    ((NROWS2 + SCAN_B - 1) / SCAN_B)   // 391

// ---------------------------------------------------------------------------
// Static scratch (no cudaMalloc allowed).
// ---------------------------------------------------------------------------
__device__ float g_x1[N_NODES * DIM];        // in @ W1   (25.6 MB)
__device__ float g_x2[N_NODES * DIM];        // in @ W2   (25.6 MB)

__device__ int  g_cnt[NROWS2];               // per-row edge counts
__device__ int  g_off[NROWS2 + 1];           // CSR row pointers
__device__ int  g_pos[NROWS2];               // scatter cursors
__device__ int  g_bsum[NBLK];                // scan block sums
__device__ int2 g_edge[2 * E_MAX];           // packed (col, val-bits)

__device__ __forceinline__ uint32_t f2tf32(float f) {
    uint32_t r;
    asm("cvt.rna.tf32.f32 %0, %1;" : "=r"(r) : "f"(f));
    return r;
}

// ---------------------------------------------------------------------------
// Dense projection on tensor cores: x = in @ W per relation (blockIdx.y).
// ---------------------------------------------------------------------------
__global__ void __launch_bounds__(256)
gemm_tf32_kernel(const float* __restrict__ in,
                 const float* __restrict__ W1,
                 const float* __restrict__ W2)
{
    __shared__ uint32_t shA[64 * A_PAD];

    const int tid  = threadIdx.x;
    const int warp = tid >> 5;
    const int lane = tid & 31;
    const int row0 = blockIdx.x * 64;
    const float* __restrict__ W    = blockIdx.y ? W2   : W1;
    float*       __restrict__ xout = blockIdx.y ? g_x2 : g_x1;

    #pragma unroll
    for (int i = 0; i < 8; ++i) {
        int idx = tid + i * 256;
        int r   = idx >> 5;
        int c4  = idx & 31;
        float4 v = make_float4(0.f, 0.f, 0.f, 0.f);
        if (row0 + r < N_NODES)
            v = __ldg(reinterpret_cast<const float4*>(in + (size_t)(row0 + r) * DIM) + c4);
        uint32_t* s = shA + r * A_PAD + c4 * 4;
        s[0] = f2tf32(v.x); s[1] = f2tf32(v.y); s[2] = f2tf32(v.z); s[3] = f2tf32(v.w);
    }
    __syncthreads();

    const int col0 = warp * 16;
    uint32_t Bf[2][16][2];
    #pragma unroll
    for (int nt = 0; nt < 2; ++nt) {
        const int n = col0 + nt * 8 + (lane >> 2);
        #pragma unroll
        for (int kk = 0; kk < 16; ++kk) {
            const int k = kk * 8 + (lane & 3);
            Bf[nt][kk][0] = f2tf32(__ldg(W + k * DIM + n));
            Bf[nt][kk][1] = f2tf32(__ldg(W + (k + 4) * DIM + n));
        }
    }

    #pragma unroll
    for (int rt = 0; rt < 4; ++rt) {
        float acc[2][4] = {};
        const uint32_t* sA = shA + (rt * 16) * A_PAD;
        #pragma unroll
        for (int kk = 0; kk < 16; ++kk) {
            const int r = lane >> 2, c = kk * 8 + (lane & 3);
            uint32_t a0 = sA[r * A_PAD + c];
            uint32_t a1 = sA[(r + 8) * A_PAD + c];
            uint32_t a2 = sA[r * A_PAD + c + 4];
            uint32_t a3 = sA[(r + 8) * A_PAD + c + 4];
            #pragma unroll
            for (int nt = 0; nt < 2; ++nt) {
                asm volatile(
                    "mma.sync.aligned.m16n8k8.row.col.f32.tf32.tf32.f32 "
                    "{%0,%1,%2,%3}, {%4,%5,%6,%7}, {%8,%9}, {%0,%1,%2,%3};"
                    : "+f"(acc[nt][0]), "+f"(acc[nt][1]),
                      "+f"(acc[nt][2]), "+f"(acc[nt][3])
                    : "r"(a0), "r"(a1), "r"(a2), "r"(a3),
                      "r"(Bf[nt][kk][0]), "r"(Bf[nt][kk][1]));
            }
        }
        const int rowa = row0 + rt * 16 + (lane >> 2);
        const int rowb = rowa + 8;
        #pragma unroll
        for (int nt = 0; nt < 2; ++nt) {
            const int c = col0 + nt * 8 + 2 * (lane & 3);
            if (rowa < N_NODES)
                *reinterpret_cast<float2*>(xout + (size_t)rowa * DIM + c) =
                    make_float2(acc[nt][0], acc[nt][1]);
            if (rowb < N_NODES)
                *reinterpret_cast<float2*>(xout + (size_t)rowb * DIM + c) =
                    make_float2(acc[nt][2], acc[nt][3]);
        }
    }
}

// ---------------------------------------------------------------------------
// CSR build.
// ---------------------------------------------------------------------------
__global__ void __launch_bounds__(256)
zero_cnt_kernel()
{
    const int i = blockIdx.x * blockDim.x + threadIdx.x;
    if (i < NROWS2) g_cnt[i] = 0;
}

// Histogram: 4 edges per thread (int4 load, 4 independent atomics -> MLP 4).
__global__ void __launch_bounds__(256)
hist4_kernel(const int* __restrict__ rows, int E, int rowbase)
{
    const int v = blockIdx.x * blockDim.x + threadIdx.x;
    const int i = v * 4;
    if (i + 3 < E) {
        const int4 r = __ldg(reinterpret_cast<const int4*>(rows) + v);
        atomicAdd(&g_cnt[rowbase + r.x], 1);
        atomicAdd(&g_cnt[rowbase + r.y], 1);
        atomicAdd(&g_cnt[rowbase + r.z], 1);
        atomicAdd(&g_cnt[rowbase + r.w], 1);
    } else {
        for (int k = i; k < E; ++k)
            atomicAdd(&g_cnt[rowbase + __ldg(rows + k)], 1);
    }
}

// Scan stage A: coalesced block-local exclusive scan of g_cnt -> g_off,
// block totals -> g_bsum.
__global__ void __launch_bounds__(SCAN_B)
scanA_kernel()
{
    __shared__ int sh[SCAN_B];
    const int t = threadIdx.x;
    const int i = blockIdx.x * SCAN_B + t;
    const int v = (i < NROWS2) ? g_cnt[i] : 0;
    sh[t] = v;
    __syncthreads();
    #pragma unroll
    for (int d = 1; d < SCAN_B; d <<= 1) {
        int u = (t >= d) ? sh[t - d] : 0;
        __syncthreads();
        sh[t] += u;
        __syncthreads();
    }
    if (i < NROWS2) g_off[i] = sh[t] - v;           // block-local exclusive
    if (t == SCAN_B - 1) g_bsum[blockIdx.x] = sh[t];
}

// Scan stage B: one block scans the 391 block sums (exclusive), writes total.
__global__ void __launch_bounds__(512)
scanB_kernel()
{
    __shared__ int sh[512];
    const int t = threadIdx.x;
    const int v = (t < NBLK) ? g_bsum[t] : 0;
    sh[t] = v;
    __syncthreads();
    #pragma unroll
    for (int d = 1; d < 512; d <<= 1) {
        int u = (t >= d) ? sh[t - d] : 0;
        __syncthreads();
        sh[t] += u;
        __syncthreads();
    }
    if (t < NBLK) g_bsum[t] = sh[t] - v;            // exclusive base per block
    if (t == 511) g_off[NROWS2] = sh[511];          // grand total (sentinel)
}

// Scan stage C: add block base, mirror into scatter cursors.
__global__ void __launch_bounds__(SCAN_B)
scanC_kernel()
{
    const int i = blockIdx.x * SCAN_B + threadIdx.x;
    if (i < NROWS2) {
        const int o = g_off[i] + g_bsum[blockIdx.x];
        g_off[i] = o;
        g_pos[i] = o;
    }
}

// Scatter: 4 edges per thread, vector loads, 4 independent ATOMGs in flight.
__global__ void __launch_bounds__(256)
scatter4_kernel(const int* __restrict__ rows, const int* __restrict__ cols,
                const float* __restrict__ vals, int E, int rowbase)
{
    const int v = blockIdx.x * blockDim.x + threadIdx.x;
    const int i = v * 4;
    if (i + 3 < E) {
        const int4   r = __ldg(reinterpret_cast<const int4*>(rows) + v);
        const int4   c = __ldg(reinterpret_cast<const int4*>(cols) + v);
        const float4 w = __ldg(reinterpret_cast<const float4*>(vals) + v);
        const int p0 = atomicAdd(&g_pos[rowbase + r.x], 1);
        const int p1 = atomicAdd(&g_pos[rowbase + r.y], 1);
        const int p2 = atomicAdd(&g_pos[rowbase + r.z], 1);
        const int p3 = atomicAdd(&g_pos[rowbase + r.w], 1);
        g_edge[p0] = make_int2(c.x, __float_as_int(w.x));
        g_edge[p1] = make_int2(c.y, __float_as_int(w.y));
        g_edge[p2] = make_int2(c.z, __float_as_int(w.z));
        g_edge[p3] = make_int2(c.w, __float_as_int(w.w));
    } else {
        for (int k = i; k < E; ++k) {
            const int p = atomicAdd(&g_pos[rowbase + __ldg(rows + k)], 1);
            g_edge[p] = make_int2(__ldg(cols + k), __float_as_int(__ldg(vals + k)));
        }
    }
}

// ---------------------------------------------------------------------------
// Segmented SpMM, warp-cooperative: one warp per output row.
// Per 32-edge chunk: ONE coalesced edge load into shared, then the inner loop
// is LDS-broadcast -> 4 INDEPENDENT float4 gathers -> FMAs (gather MLP ~4).
// Fused ReLU, single non-atomic store.
// ---------------------------------------------------------------------------
__device__ __forceinline__ void row_accum(const float* __restrict__ x,
                                          int s, int e, int lane,
                                          int* __restrict__ shc,
                                          int* __restrict__ shv,
                                          float4& acc)
{
    for (int i = s; i < e; i += 32) {
        const int idx = i + lane;
        if (idx < e) {
            const int2 t = __ldg(&g_edge[idx]);
            shc[lane] = t.x;
            shv[lane] = t.y;
        }
        __syncwarp();
        const int m = min(e - i, 32);
        int j = 0;
        for (; j + 4 <= m; j += 4) {
            const int c0 = shc[j],     c1 = shc[j + 1];
            const int c2 = shc[j + 2], c3 = shc[j + 3];
            const float4 x0 = __ldg(reinterpret_cast<const float4*>(x + (size_t)c0 * DIM) + lane);
            const float4 x1 = __ldg(reinterpret_cast<const float4*>(x + (size_t)c1 * DIM) + lane);
            const float4 x2 = __ldg(reinterpret_cast<const float4*>(x + (size_t)c2 * DIM) + lane);
            const float4 x3 = __ldg(reinterpret_cast<const float4*>(x + (size_t)c3 * DIM) + lane);
            const float v0 = __int_as_float(shv[j]);
            const float v1 = __int_as_float(shv[j + 1]);
            const float v2 = __int_as_float(shv[j + 2]);
            const float v3 = __int_as_float(shv[j + 3]);
            acc.x = fmaf(v0, x0.x, acc.x); acc.y = fmaf(v0, x0.y, acc.y);
            acc.z = fmaf(v0, x0.z, acc.z); acc.w = fmaf(v0, x0.w, acc.w);
            acc.x = fmaf(v1, x1.x, acc.x); acc.y = fmaf(v1, x1.y, acc.y);
            acc.z = fmaf(v1, x1.z, acc.z); acc.w = fmaf(v1, x1.w, acc.w);
            acc.x = fmaf(v2, x2.x, acc.x); acc.y = fmaf(v2, x2.y, acc.y);
            acc.z = fmaf(v2, x2.z, acc.z); acc.w = fmaf(v2, x2.w, acc.w);
            acc.x = fmaf(v3, x3.x, acc.x); acc.y = fmaf(v3, x3.y, acc.y);
            acc.z = fmaf(v3, x3.z, acc.z); acc.w = fmaf(v3, x3.w, acc.w);
        }
        for (; j < m; ++j) {
            const int   c  = shc[j];
            const float v  = __int_as_float(shv[j]);
            const float4 xv = __ldg(reinterpret_cast<const float4*>(x + (size_t)c * DIM) + lane);
            acc.x = fmaf(v, xv.x, acc.x); acc.y = fmaf(v, xv.y, acc.y);
            acc.z = fmaf(v, xv.z, acc.z); acc.w = fmaf(v, xv.w, acc.w);
        }
        __syncwarp();
    }
}

__global__ void __launch_bounds__(256)
spmm_csr_kernel(float* __restrict__ out)
{
    __shared__ int shc[8][32];
    __shared__ int shv[8][32];

    const int warp = threadIdx.x >> 5;
    const int lane = threadIdx.x & 31;
    const int row  = blockIdx.x * 8 + warp;
    if (row >= N_NODES) return;

    float4 acc = make_float4(0.f, 0.f, 0.f, 0.f);

    row_accum(g_x1, g_off[row],           g_off[row + 1],
              lane, shc[warp], shv[warp], acc);
    row_accum(g_x2, g_off[N_NODES + row], g_off[N_NODES + row + 1],
              lane, shc[warp], shv[warp], acc);

    acc.x = fmaxf(acc.x, 0.f); acc.y = fmaxf(acc.y, 0.f);
    acc.z = fmaxf(acc.z, 0.f); acc.w = fmaxf(acc.w, 0.f);
    reinterpret_cast<float4*>(out + (size_t)row * DIM)[lane] = acc;
}

// ---------------------------------------------------------------------------
// Entry point. Inputs (metadata order):
//   0 inputs[N,128] f32 | 1 adj1_rows i32 | 2 adj1_cols i32 | 3 adj1_vals f32
//   4 adj2_rows i32 | 5 adj2_cols i32 | 6 adj2_vals f32
//   7 weights_1[128,128] f32 | 8 weights_2[128,128] f32
// Output: [N,128] f32.
// ---------------------------------------------------------------------------
extern "C" void kernel_launch(void* const* d_in, const int* in_sizes, int n_in,
                              void* d_out, int out_size)
{
    const float* in  = (const float*)d_in[0];
    const int*   a1r = (const int*)  d_in[1];
    const int*   a1c = (const int*)  d_in[2];
    const float* a1v = (const float*)d_in[3];
    const int*   a2r = (const int*)  d_in[4];
    const int*   a2c = (const int*)  d_in[5];
    const float* a2v = (const float*)d_in[6];
    const float* W1  = (const float*)d_in[7];
    const float* W2  = (const float*)d_in[8];
    float*       out = (float*)d_out;

    const int E1 = in_sizes[1];
    const int E2 = in_sizes[4];

    const int hb1 = (E1 / 4 + 256) / 256;   // covers vec body + tail
    const int hb2 = (E2 / 4 + 256) / 256;

    // CSR build (counting sort by flattened row id).
    zero_cnt_kernel<<<(NROWS2 + 255) / 256, 256>>>();
    hist4_kernel<<<hb1, 256>>>(a1r, E1, 0);
    hist4_kernel<<<hb2, 256>>>(a2r, E2, N_NODES);
    scanA_kernel<<<NBLK, SCAN_B>>>();
    scanB_kernel<<<1, 512>>>();
    scanC_kernel<<<NBLK, SCAN_B>>>();
    scatter4_kernel<<<hb1, 256>>>(a1r, a1c, a1v, E1, 0);
    scatter4_kernel<<<hb2, 256>>>(a2r, a2c, a2v, E2, N_NODES);

    // Tensor-core projections (both relations, grid.y = relation).
    dim3 ggrid((N_NODES + 63) / 64, 2);
    gemm_tf32_kernel<<<ggrid, 256>>>(in, W1, W2);

    // Segmented SpMM + fused ReLU: one warp per row.
    spmm_csr_kernel<<<(N_NODES + 7) / 8, 256>>>(out);
}

// round 7
// speedup vs baseline: 2.1321x; 1.0719x over previous
#include <cuda_runtime.h>
#include <stdint.h>

#define N_NODES 50000
#define DIM     128        // D == O == 128
#define E_MAX   800016     // per-relation edge capacity (problem fixes E=800000)
#define A_PAD   132        // shared A row stride (bank-conflict-free fragments)

#define NROWS2  (2 * N_NODES)                 // flattened rows (2 relations)
#define SCAN_B  256
#define NBLK    ((NROWS2 + SCAN_B - 1) / SCAN_B)   // 391

// ---------------------------------------------------------------------------
// Static scratch (no cudaMalloc allowed).
// ---------------------------------------------------------------------------
__device__ float g_x1[N_NODES * DIM];        // in @ W1   (25.6 MB)
__device__ float g_x2[N_NODES * DIM];        // in @ W2   (25.6 MB)

__device__ int  g_cnt[NROWS2];               // per-row edge counts
__device__ int  g_off[NROWS2 + 1];           // CSR row pointers
__device__ int  g_pos[NROWS2];               // scatter cursors
__device__ int  g_bsum[NBLK];                // scan block sums
__device__ int2 g_edge[2 * E_MAX];           // packed (col, val-bits)

__device__ __forceinline__ uint32_t f2tf32(float f) {
    uint32_t r;
    asm("cvt.rna.tf32.f32 %0, %1;" : "=r"(r) : "f"(f));
    return r;
}

// ---------------------------------------------------------------------------
// Dense projection on tensor cores: x = in @ W per relation (blockIdx.y).
// 2 row-tiles (128 rows) per block: B fragments (64 regs/warp) are loaded
// ONCE and reused across both tiles, halving the prologue-per-tile cost and
// the wave count (782 blocks vs 1564).
// ---------------------------------------------------------------------------
__global__ void __launch_bounds__(256)
gemm_tf32_kernel(const float* __restrict__ in,
                 const float* __restrict__ W1,
                 const float* __restrict__ W2)
{
    __shared__ uint32_t shA[64 * A_PAD];

    const int tid  = threadIdx.x;
    const int warp = tid >> 5;
    const int lane = tid & 31;
    const float* __restrict__ W    = blockIdx.y ? W2   : W1;
    float*       __restrict__ xout = blockIdx.y ? g_x2 : g_x1;

    // B fragments for this warp's 16 columns, all 16 K-steps, both n-tiles.
    // m16n8k8 B (col): b0 -> (k = lane%4, n = lane>>2), b1 -> k+4.
    const int col0 = warp * 16;
    uint32_t Bf[2][16][2];
    #pragma unroll
    for (int nt = 0; nt < 2; ++nt) {
        const int n = col0 + nt * 8 + (lane >> 2);
        #pragma unroll
        for (int kk = 0; kk < 16; ++kk) {
            const int k = kk * 8 + (lane & 3);
            Bf[nt][kk][0] = f2tf32(__ldg(W + k * DIM + n));
            Bf[nt][kk][1] = f2tf32(__ldg(W + (k + 4) * DIM + n));
        }
    }

    #pragma unroll
    for (int t = 0; t < 2; ++t) {
        const int row0 = blockIdx.x * 128 + t * 64;

        // Stage A tile (64 x 128) -> shared, rounding to tf32 once.
        #pragma unroll
        for (int i = 0; i < 8; ++i) {
            int idx = tid + i * 256;
            int r   = idx >> 5;
            int c4  = idx & 31;
            float4 v = make_float4(0.f, 0.f, 0.f, 0.f);
            if (row0 + r < N_NODES)
                v = __ldg(reinterpret_cast<const float4*>(in + (size_t)(row0 + r) * DIM) + c4);
            uint32_t* s = shA + r * A_PAD + c4 * 4;
            s[0] = f2tf32(v.x); s[1] = f2tf32(v.y); s[2] = f2tf32(v.z); s[3] = f2tf32(v.w);
        }
        __syncthreads();

        #pragma unroll
        for (int rt = 0; rt < 4; ++rt) {
            float acc[2][4] = {};
            const uint32_t* sA = shA + (rt * 16) * A_PAD;
            #pragma unroll
            for (int kk = 0; kk < 16; ++kk) {
                const int r = lane >> 2, c = kk * 8 + (lane & 3);
                uint32_t a0 = sA[r * A_PAD + c];
                uint32_t a1 = sA[(r + 8) * A_PAD + c];
                uint32_t a2 = sA[r * A_PAD + c + 4];
                uint32_t a3 = sA[(r + 8) * A_PAD + c + 4];
                #pragma unroll
                for (int nt = 0; nt < 2; ++nt) {
                    asm volatile(
                        "mma.sync.aligned.m16n8k8.row.col.f32.tf32.tf32.f32 "
                        "{%0,%1,%2,%3}, {%4,%5,%6,%7}, {%8,%9}, {%0,%1,%2,%3};"
                        : "+f"(acc[nt][0]), "+f"(acc[nt][1]),
                          "+f"(acc[nt][2]), "+f"(acc[nt][3])
                        : "r"(a0), "r"(a1), "r"(a2), "r"(a3),
                          "r"(Bf[nt][kk][0]), "r"(Bf[nt][kk][1]));
                }
            }
            const int rowa = row0 + rt * 16 + (lane >> 2);
            const int rowb = rowa + 8;
            #pragma unroll
            for (int nt = 0; nt < 2; ++nt) {
                const int c = col0 + nt * 8 + 2 * (lane & 3);
                if (rowa < N_NODES)
                    *reinterpret_cast<float2*>(xout + (size_t)rowa * DIM + c) =
                        make_float2(acc[nt][0], acc[nt][1]);
                if (rowb < N_NODES)
                    *reinterpret_cast<float2*>(xout + (size_t)rowb * DIM + c) =
                        make_float2(acc[nt][2], acc[nt][3]);
            }
        }
        __syncthreads();   // shA reused by next tile
    }
}

// ---------------------------------------------------------------------------
// CSR build.
// ---------------------------------------------------------------------------
__global__ void __launch_bounds__(256)
zero_cnt_kernel()
{
    const int i = blockIdx.x * blockDim.x + threadIdx.x;
    if (i < NROWS2) g_cnt[i] = 0;
}

// Histogram over BOTH relations in one launch: thread owns one 4-edge vector
// group of either relation (flattened group id). 4 independent ATOMGs.
__global__ void __launch_bounds__(256)
hist4_kernel(const int* __restrict__ r1, const int* __restrict__ r2,
             int E1, int E2)
{
    const int V1 = (E1 + 3) >> 2;
    const int V2 = (E2 + 3) >> 2;
    int v = blockIdx.x * blockDim.x + threadIdx.x;
    const int* rows; int E, rowbase;
    if (v < V1)            { rows = r1; E = E1; rowbase = 0; }
    else if (v < V1 + V2)  { rows = r2; E = E2; rowbase = N_NODES; v -= V1; }
    else return;

    const int i = v * 4;
    if (i + 3 < E) {
        const int4 r = __ldg(reinterpret_cast<const int4*>(rows) + v);
        atomicAdd(&g_cnt[rowbase + r.x], 1);
        atomicAdd(&g_cnt[rowbase + r.y], 1);
        atomicAdd(&g_cnt[rowbase + r.z], 1);
        atomicAdd(&g_cnt[rowbase + r.w], 1);
    } else {
        for (int k = i; k < E; ++k)
            atomicAdd(&g_cnt[rowbase + __ldg(rows + k)], 1);
    }
}

// Scan stage A: coalesced block-local exclusive scan of g_cnt -> g_off.
__global__ void __launch_bounds__(SCAN_B)
scanA_kernel()
{
    __shared__ int sh[SCAN_B];
    const int t = threadIdx.x;
    const int i = blockIdx.x * SCAN_B + t;
    const int v = (i < NROWS2) ? g_cnt[i] : 0;
    sh[t] = v;
    __syncthreads();
    #pragma unroll
    for (int d = 1; d < SCAN_B; d <<= 1) {
        int u = (t >= d) ? sh[t - d] : 0;
        __syncthreads();
        sh[t] += u;
        __syncthreads();
    }
    if (i < NROWS2) g_off[i] = sh[t] - v;
    if (t == SCAN_B - 1) g_bsum[blockIdx.x] = sh[t];
}

// Scan stage B: one block scans the 391 block sums (exclusive) + total.
__global__ void __launch_bounds__(512)
scanB_kernel()
{
    __shared__ int sh[512];
    const int t = threadIdx.x;
    const int v = (t < NBLK) ? g_bsum[t] : 0;
    sh[t] = v;
    __syncthreads();
    #pragma unroll
    for (int d = 1; d < 512; d <<= 1) {
        int u = (t >= d) ? sh[t - d] : 0;
        __syncthreads();
        sh[t] += u;
        __syncthreads();
    }
    if (t < NBLK) g_bsum[t] = sh[t] - v;
    if (t == 511) g_off[NROWS2] = sh[511];
}

// Scan stage C: add block base, mirror into scatter cursors.
__global__ void __launch_bounds__(SCAN_B)
scanC_kernel()
{
    const int i = blockIdx.x * SCAN_B + threadIdx.x;
    if (i < NROWS2) {
        const int o = g_off[i] + g_bsum[blockIdx.x];
        g_off[i] = o;
        g_pos[i] = o;
    }
}

// Scatter over BOTH relations in one launch (same flattened group scheme).
__global__ void __launch_bounds__(256)
scatter4_kernel(const int* __restrict__ r1, const int* __restrict__ c1,
                const float* __restrict__ v1,
                const int* __restrict__ r2, const int* __restrict__ c2,
                const float* __restrict__ v2,
                int E1, int E2)
{
    const int V1 = (E1 + 3) >> 2;
    const int V2 = (E2 + 3) >> 2;
    int v = blockIdx.x * blockDim.x + threadIdx.x;
    const int* rows; const int* cols; const float* vals; int E, rowbase;
    if (v < V1)           { rows = r1; cols = c1; vals = v1; E = E1; rowbase = 0; }
    else if (v < V1 + V2) { rows = r2; cols = c2; vals = v2; E = E2; rowbase = N_NODES; v -= V1; }
    else return;

    const int i = v * 4;
    if (i + 3 < E) {
        const int4   r = __ldg(reinterpret_cast<const int4*>(rows) + v);
        const int4   c = __ldg(reinterpret_cast<const int4*>(cols) + v);
        const float4 w = __ldg(reinterpret_cast<const float4*>(vals) + v);
        const int p0 = atomicAdd(&g_pos[rowbase + r.x], 1);
        const int p1 = atomicAdd(&g_pos[rowbase + r.y], 1);
        const int p2 = atomicAdd(&g_pos[rowbase + r.z], 1);
        const int p3 = atomicAdd(&g_pos[rowbase + r.w], 1);
        g_edge[p0] = make_int2(c.x, __float_as_int(w.x));
        g_edge[p1] = make_int2(c.y, __float_as_int(w.y));
        g_edge[p2] = make_int2(c.z, __float_as_int(w.z));
        g_edge[p3] = make_int2(c.w, __float_as_int(w.w));
    } else {
        for (int k = i; k < E; ++k) {
            const int p = atomicAdd(&g_pos[rowbase + __ldg(rows + k)], 1);
            g_edge[p] = make_int2(__ldg(cols + k), __float_as_int(__ldg(vals + k)));
        }
    }
}

// ---------------------------------------------------------------------------
// Segmented SpMM, warp-cooperative: one warp per output row.
// Per 32-edge chunk: ONE coalesced edge load into shared, then the inner loop
// is LDS-broadcast -> 4 INDEPENDENT float4 gathers -> FMAs (gather MLP ~4).
// Fused ReLU, single non-atomic store. At the LTS roofline (~819 MB of L2
// gather traffic).
// ---------------------------------------------------------------------------
__device__ __forceinline__ void row_accum(const float* __restrict__ x,
                                          int s, int e, int lane,
                                          int* __restrict__ shc,
                                          int* __restrict__ shv,
                                          float4& acc)
{
    for (int i = s; i < e; i += 32) {
        const int idx = i + lane;
        if (idx < e) {
            const int2 t = __ldg(&g_edge[idx]);
            shc[lane] = t.x;
            shv[lane] = t.y;
        }
        __syncwarp();
        const int m = min(e - i, 32);
        int j = 0;
        for (; j + 4 <= m; j += 4) {
            const int c0 = shc[j],     c1 = shc[j + 1];
            const int c2 = shc[j + 2], c3 = shc[j + 3];
            const float4 x0 = __ldg(reinterpret_cast<const float4*>(x + (size_t)c0 * DIM) + lane);
            const float4 x1 = __ldg(reinterpret_cast<const float4*>(x + (size_t)c1 * DIM) + lane);
            const float4 x2 = __ldg(reinterpret_cast<const float4*>(x + (size_t)c2 * DIM) + lane);
            const float4 x3 = __ldg(reinterpret_cast<const float4*>(x + (size_t)c3 * DIM) + lane);
            const float v0 = __int_as_float(shv[j]);
            const float v1 = __int_as_float(shv[j + 1]);
            const float v2 = __int_as_float(shv[j + 2]);
            const float v3 = __int_as_float(shv[j + 3]);
            acc.x = fmaf(v0, x0.x, acc.x); acc.y = fmaf(v0, x0.y, acc.y);
            acc.z = fmaf(v0, x0.z, acc.z); acc.w = fmaf(v0, x0.w, acc.w);
            acc.x = fmaf(v1, x1.x, acc.x); acc.y = fmaf(v1, x1.y, acc.y);
            acc.z = fmaf(v1, x1.z, acc.z); acc.w = fmaf(v1, x1.w, acc.w);
            acc.x = fmaf(v2, x2.x, acc.x); acc.y = fmaf(v2, x2.y, acc.y);
            acc.z = fmaf(v2, x2.z, acc.z); acc.w = fmaf(v2, x2.w, acc.w);
            acc.x = fmaf(v3, x3.x, acc.x); acc.y = fmaf(v3, x3.y, acc.y);
            acc.z = fmaf(v3, x3.z, acc.z); acc.w = fmaf(v3, x3.w, acc.w);
        }
        for (; j < m; ++j) {
            const int   c  = shc[j];
            const float v  = __int_as_float(shv[j]);
            const float4 xv = __ldg(reinterpret_cast<const float4*>(x + (size_t)c * DIM) + lane);
            acc.x = fmaf(v, xv.x, acc.x); acc.y = fmaf(v, xv.y, acc.y);
            acc.z = fmaf(v, xv.z, acc.z); acc.w = fmaf(v, xv.w, acc.w);
        }
        __syncwarp();
    }
}

__global__ void __launch_bounds__(256)
spmm_csr_kernel(float* __restrict__ out)
{
    __shared__ int shc[8][32];
    __shared__ int shv[8][32];

    const int warp = threadIdx.x >> 5;
    const int lane = threadIdx.x & 31;
    const int row  = blockIdx.x * 8 + warp;
    if (row >= N_NODES) return;

    float4 acc = make_float4(0.f, 0.f, 0.f, 0.f);

    row_accum(g_x1, g_off[row],           g_off[row + 1],
              lane, shc[warp], shv[warp], acc);
    row_accum(g_x2, g_off[N_NODES + row], g_off[N_NODES + row + 1],
              lane, shc[warp], shv[warp], acc);

    acc.x = fmaxf(acc.x, 0.f); acc.y = fmaxf(acc.y, 0.f);
    acc.z = fmaxf(acc.z, 0.f); acc.w = fmaxf(acc.w, 0.f);
    reinterpret_cast<float4*>(out + (size_t)row * DIM)[lane] = acc;
}

// ---------------------------------------------------------------------------
// Entry point. Inputs (metadata order):
//   0 inputs[N,128] f32 | 1 adj1_rows i32 | 2 adj1_cols i32 | 3 adj1_vals f32
//   4 adj2_rows i32 | 5 adj2_cols i32 | 6 adj2_vals f32
//   7 weights_1[128,128] f32 | 8 weights_2[128,128] f32
// Output: [N,128] f32.
// ---------------------------------------------------------------------------
extern "C" void kernel_launch(void* const* d_in, const int* in_sizes, int n_in,
                              void* d_out, int out_size)
{
    const float* in  = (const float*)d_in[0];
    const int*   a1r = (const int*)  d_in[1];
    const int*   a1c = (const int*)  d_in[2];
    const float* a1v = (const float*)d_in[3];
    const int*   a2r = (const int*)  d_in[4];
    const int*   a2c = (const int*)  d_in[5];
    const float* a2v = (const float*)d_in[6];
    const float* W1  = (const float*)d_in[7];
    const float* W2  = (const float*)d_in[8];
    float*       out = (float*)d_out;

    const int E1 = in_sizes[1];
    const int E2 = in_sizes[4];

    const int Vtot = (E1 + 3) / 4 + (E2 + 3) / 4;
    const int eblk = (Vtot + 255) / 256;

    // CSR build (counting sort by flattened row id), 6 launches.
    zero_cnt_kernel<<<(NROWS2 + 255) / 256, 256>>>();
    hist4_kernel<<<eblk, 256>>>(a1r, a2r, E1, E2);
    scanA_kernel<<<NBLK, SCAN_B>>>();
    scanB_kernel<<<1, 512>>>();
    scanC_kernel<<<NBLK, SCAN_B>>>();
    scatter4_kernel<<<eblk, 256>>>(a1r, a1c, a1v, a2r, a2c, a2v, E1, E2);

    // Tensor-core projections: 128 rows/block, B regs reused across 2 tiles.
    dim3 ggrid((N_NODES + 127) / 128, 2);
    gemm_tf32_kernel<<<ggrid, 256>>>(in, W1, W2);

    // Segmented SpMM + fused ReLU: one warp per row.
    spmm_csr_kernel<<<(N_NODES + 7) / 8, 256>>>(out);
}